// round 1
// baseline (speedup 1.0000x reference)
#include <cuda_runtime.h>
#include <cuda_bf16.h>

// Problem constants
#define KSZ   9
#define PAD   4
#define H     256
#define W     256
#define HO    248          // H - 2*PAD
#define WO    248
#define B     4
#define PLANE (H * W)      // 65536

// Tiling
#define TW    32           // output tile width
#define TH    8            // output tile height
#define SW    (TW + 8)     // 40 smem cols (halo = K-1 = 8)
#define SH    (TH + 8)     // 16 smem rows
#define NTHR  256

#define GX    8            // ceil(248/32)
#define GY    31           // 248/8
#define NBLK  (GX * GY * B)   // 992

// -100 * log2(e)  : exp(-color/0.01) = 2^(color * NC1)
#define NC1   (-144.26950408889634f)
// 1/9 * log2(e)   : dist[k] = 2^(-d2 * DC)
#define DC    (1.4426950408889634f / 9.0f)

static __device__ float g_bsums[NBLK];

__device__ __forceinline__ float ex2f(float v) {
    float r;
    asm("ex2.approx.f32 %0, %1;" : "=f"(r) : "f"(v));
    return r;
}

__global__ __launch_bounds__(NTHR)
void potts_main(const float* __restrict__ x, const float* __restrict__ y) {
    __shared__ float s[5][SH][SW];   // planes: x0,x1,x2,y0,y1  (12.8 KB)

    const int b   = blockIdx.z;
    const int tx0 = blockIdx.x * TW;
    const int ty0 = blockIdx.y * TH;
    const int tid = threadIdx.x;

    const float* xb = x + (size_t)b * 3 * PLANE;
    const float* yb = y + (size_t)b * 2 * PLANE;

    // Cooperative halo load. Rows: ty0 max = 240, +15 = 255 -> always in range.
    // Cols can exceed 255 on the last tile column; clamp (those values are only
    // consumed by out-of-range (masked) output threads anyway).
    for (int i = tid; i < 5 * SH * SW; i += NTHR) {
        int p  = i / (SH * SW);
        int r  = (i / SW) % SH;
        int c  = i % SW;
        int gy = ty0 + r;
        int gx = min(tx0 + c, W - 1);
        float v = (p < 3) ? xb[p * PLANE + gy * W + gx]
                          : yb[(p - 3) * PLANE + gy * W + gx];
        s[p][r][c] = v;
    }
    __syncthreads();

    const int lx = tid & (TW - 1);
    const int ly = tid >> 5;
    const int wo = tx0 + lx;

    float acc = 0.0f;
    if (wo < WO) {
        const float xc0 = s[0][ly + PAD][lx + PAD];
        const float xc1 = s[1][ly + PAD][lx + PAD];
        const float xc2 = s[2][ly + PAD][lx + PAD];
        const float y0c = s[3][ly + PAD][lx + PAD];
        const float y1c = s[4][ly + PAD][lx + PAD];

        #pragma unroll
        for (int ki = 0; ki < KSZ; ki++) {
            const float* r0 = &s[0][ly + ki][lx];
            const float* r1 = &s[1][ly + ki][lx];
            const float* r2 = &s[2][ly + ki][lx];
            const float* r3 = &s[3][ly + ki][lx];
            const float* r4 = &s[4][ly + ki][lx];
            #pragma unroll
            for (int kj = 0; kj < KSZ; kj++) {
                float d0 = xc0 - r0[kj];
                float d1 = xc1 - r1[kj];
                float d2 = xc2 - r2[kj];
                float color = fmaf(d2, d2, fmaf(d1, d1, d0 * d0));
                // compile-time constant per (ki,kj): -d2_spatial/9*log2e
                float c0k = -(float)((ki - PAD) * (ki - PAD) +
                                     (kj - PAD) * (kj - PAD)) * DC;
                float w = ex2f(fmaf(color, NC1, c0k));
                float p = fmaf(y0c, r4[kj], y1c * r3[kj]);
                acc = fmaf(w, p, acc);
            }
        }
    }

    // Deterministic block reduction
    #pragma unroll
    for (int off = 16; off > 0; off >>= 1)
        acc += __shfl_down_sync(0xffffffffu, acc, off);

    __shared__ float wsum[NTHR / 32];
    if (lx == 0) wsum[ly] = acc;
    __syncthreads();
    if (tid == 0) {
        float t = 0.0f;
        #pragma unroll
        for (int i = 0; i < NTHR / 32; i++) t += wsum[i];
        g_bsums[blockIdx.x + GX * (blockIdx.y + GY * blockIdx.z)] = t;
    }
}

__global__ __launch_bounds__(NTHR)
void potts_reduce(float* __restrict__ out) {
    const int tid = threadIdx.x;
    double acc = 0.0;
    for (int i = tid; i < NBLK; i += NTHR) acc += (double)g_bsums[i];

    #pragma unroll
    for (int off = 16; off > 0; off >>= 1)
        acc += __shfl_down_sync(0xffffffffu, acc, off);

    __shared__ double wsum[NTHR / 32];
    if ((tid & 31) == 0) wsum[tid >> 5] = acc;
    __syncthreads();
    if (tid == 0) {
        double t = 0.0;
        #pragma unroll
        for (int i = 0; i < NTHR / 32; i++) t += wsum[i];
        // mean over B * 81 * HO * WO for both loss terms combined
        const double scale = 1.0 / ((double)B * 81.0 * (double)HO * (double)WO);
        out[0] = (float)(t * scale);
    }
}

extern "C" void kernel_launch(void* const* d_in, const int* in_sizes, int n_in,
                              void* d_out, int out_size) {
    const float* x = (const float*)d_in[0];   // [4,3,256,256]
    const float* y = (const float*)d_in[1];   // [4,2,256,256]
    float* out = (float*)d_out;

    dim3 grid(GX, GY, B);
    potts_main<<<grid, NTHR>>>(x, y);
    potts_reduce<<<1, NTHR>>>(out);
}

// round 2
// speedup vs baseline: 1.1257x; 1.1257x over previous
#include <cuda_runtime.h>
#include <cuda_bf16.h>

// Problem constants
#define KSZ   9
#define PAD   4
#define H     256
#define W     256
#define HO    248
#define WO    248
#define B     4
#define PLANE (H * W)

// Tiling: each block computes a 64x8 output tile; warp = one row, 2 cols/lane.
#define TW    64
#define TH    8
#define SW    (TW + 8)     // 72
#define SH    (TH + 8)     // 16
#define NTHR  256

#define GX    4            // ceil(248/64)
#define GY    31
#define NBLK  (GX * GY * B)   // 496

// -100 * log2(e)  : exp(-color/0.01) = 2^(color * NC1)
#define NC1   (-144.26950408889634f)
// log2(e)/9       : dist = 2^(-d2_spatial * DC)
#define DC    (1.4426950408889634f / 9.0f)

typedef unsigned long long ull;

static __device__ float        g_bsums[NBLK];
static __device__ unsigned int g_count = 0;

__device__ __forceinline__ float ex2f(float v) {
    float r;
    asm("ex2.approx.f32 %0, %1;" : "=f"(r) : "f"(v));
    return r;
}
__device__ __forceinline__ ull pk(float lo, float hi) {
    ull r;
    asm("mov.b64 %0, {%1, %2};" : "=l"(r) : "f"(lo), "f"(hi));
    return r;
}
__device__ __forceinline__ void upk(ull v, float& lo, float& hi) {
    asm("mov.b64 {%0, %1}, %2;" : "=f"(lo), "=f"(hi) : "l"(v));
}
__device__ __forceinline__ ull f2add(ull a, ull b) {
    ull r;
    asm("add.rn.f32x2 %0, %1, %2;" : "=l"(r) : "l"(a), "l"(b));
    return r;
}
__device__ __forceinline__ ull f2mul(ull a, ull b) {
    ull r;
    asm("mul.rn.f32x2 %0, %1, %2;" : "=l"(r) : "l"(a), "l"(b));
    return r;
}
__device__ __forceinline__ ull f2fma(ull a, ull b, ull c) {
    ull r;
    asm("fma.rn.f32x2 %0, %1, %2, %3;" : "=l"(r) : "l"(a), "l"(b), "l"(c));
    return r;
}

__global__ __launch_bounds__(NTHR, 2)
void potts_fused(const float* __restrict__ x, const float* __restrict__ y,
                 float* __restrict__ out) {
    __shared__ float s[5][SH][SW];   // x0,x1,x2,y0,y1 -> 23040 B

    const int b   = blockIdx.z;
    const int tx0 = blockIdx.x * TW;
    const int ty0 = blockIdx.y * TH;
    const int tid = threadIdx.x;

    const float* xb = x + (size_t)b * 3 * PLANE;
    const float* yb = y + (size_t)b * 2 * PLANE;

    // Cooperative halo load. Rows always in [0,256); cols clamped (consumed
    // only through zeroed centers for invalid outputs).
    for (int i = tid; i < 5 * SH * SW; i += NTHR) {
        int p  = i / (SH * SW);
        int r  = (i / SW) % SH;
        int c  = i % SW;
        int gy = ty0 + r;
        int gx = min(tx0 + c, W - 1);
        float v = (p < 3) ? xb[p * PLANE + gy * W + gx]
                          : yb[(p - 3) * PLANE + gy * W + gx];
        s[p][r][c] = v;
    }
    __syncthreads();

    const int lane = tid & 31;
    const int ly   = tid >> 5;          // 0..7
    const int lx2  = lane * 2;          // tile-local col of out0
    const int col0 = tx0 + lx2;
    const bool v0  = (col0 < WO);
    const bool v1  = (col0 + 1 < WO);

    // Negated centers, packed (out0, out1)
    const ull negc0 = pk(-s[0][ly + PAD][lx2 + PAD], -s[0][ly + PAD][lx2 + 1 + PAD]);
    const ull negc1 = pk(-s[1][ly + PAD][lx2 + PAD], -s[1][ly + PAD][lx2 + 1 + PAD]);
    const ull negc2 = pk(-s[2][ly + PAD][lx2 + PAD], -s[2][ly + PAD][lx2 + 1 + PAD]);
    // Mask centers (zeroing kills contributions from invalid columns)
    const float y0c0 = v0 ? s[3][ly + PAD][lx2 + PAD]     : 0.0f;
    const float y0c1 = v1 ? s[3][ly + PAD][lx2 + 1 + PAD] : 0.0f;
    const float y1c0 = v0 ? s[4][ly + PAD][lx2 + PAD]     : 0.0f;
    const float y1c1 = v1 ? s[4][ly + PAD][lx2 + 1 + PAD] : 0.0f;

    ull accA = 0ull;   // packed Sum w * y1_neighbor
    ull accB = 0ull;   // packed Sum w * y0_neighbor

    #pragma unroll
    for (int ki = 0; ki < KSZ; ki++) {
        const int row = ly + ki;
        // Load 10 contiguous floats per plane as 5x float2 (8B aligned)
        float vx0[10], vx1[10], vx2[10], vy0[10], vy1[10];
        #pragma unroll
        for (int m = 0; m < 5; m++) {
            float2 t;
            t = *(const float2*)&s[0][row][lx2 + 2 * m]; vx0[2*m] = t.x; vx0[2*m+1] = t.y;
            t = *(const float2*)&s[1][row][lx2 + 2 * m]; vx1[2*m] = t.x; vx1[2*m+1] = t.y;
            t = *(const float2*)&s[2][row][lx2 + 2 * m]; vx2[2*m] = t.x; vx2[2*m+1] = t.y;
            t = *(const float2*)&s[3][row][lx2 + 2 * m]; vy0[2*m] = t.x; vy0[2*m+1] = t.y;
            t = *(const float2*)&s[4][row][lx2 + 2 * m]; vy1[2*m] = t.x; vy1[2*m+1] = t.y;
        }
        #pragma unroll
        for (int kj = 0; kj < KSZ; kj++) {
            ull n0 = pk(vx0[kj], vx0[kj + 1]);
            ull n1 = pk(vx1[kj], vx1[kj + 1]);
            ull n2 = pk(vx2[kj], vx2[kj + 1]);
            ull d0 = f2add(n0, negc0);
            ull d1 = f2add(n1, negc1);
            ull d2 = f2add(n2, negc2);
            ull c  = f2mul(d0, d0);
            c = f2fma(d1, d1, c);
            c = f2fma(d2, d2, c);
            float clo, chi;
            upk(c, clo, chi);
            const float c0k = -(float)((ki - PAD) * (ki - PAD) +
                                       (kj - PAD) * (kj - PAD)) * DC;
            float wlo = ex2f(fmaf(clo, NC1, c0k));
            float whi = ex2f(fmaf(chi, NC1, c0k));
            ull w = pk(wlo, whi);
            accA = f2fma(w, pk(vy1[kj], vy1[kj + 1]), accA);
            accB = f2fma(w, pk(vy0[kj], vy0[kj + 1]), accB);
        }
    }

    float a0, a1, b0, b1;
    upk(accA, a0, a1);
    upk(accB, b0, b1);
    float acc = fmaf(y0c0, a0, fmaf(y1c0, b0, fmaf(y0c1, a1, y1c1 * b1)));

    // Deterministic block reduction
    #pragma unroll
    for (int off = 16; off > 0; off >>= 1)
        acc += __shfl_down_sync(0xffffffffu, acc, off);

    __shared__ float wsum[NTHR / 32];
    if (lane == 0) wsum[ly] = acc;
    __syncthreads();

    __shared__ bool is_last;
    if (tid == 0) {
        float t = 0.0f;
        #pragma unroll
        for (int i = 0; i < NTHR / 32; i++) t += wsum[i];
        const int bid = blockIdx.x + GX * (blockIdx.y + GY * blockIdx.z);
        g_bsums[bid] = t;
        __threadfence();
        unsigned int old = atomicAdd(&g_count, 1u);
        is_last = (old == (unsigned)(NBLK - 1));
    }
    __syncthreads();

    if (is_last) {
        __threadfence();
        double dacc = 0.0;
        for (int i = tid; i < NBLK; i += NTHR) dacc += (double)g_bsums[i];
        #pragma unroll
        for (int off = 16; off > 0; off >>= 1)
            dacc += __shfl_down_sync(0xffffffffu, dacc, off);
        __shared__ double dsum[NTHR / 32];
        if (lane == 0) dsum[ly] = dacc;
        __syncthreads();
        if (tid == 0) {
            double t = 0.0;
            #pragma unroll
            for (int i = 0; i < NTHR / 32; i++) t += dsum[i];
            const double scale = 1.0 / ((double)B * 81.0 * (double)HO * (double)WO);
            out[0] = (float)(t * scale);
            g_count = 0;   // reset for next graph replay
        }
    }
}

extern "C" void kernel_launch(void* const* d_in, const int* in_sizes, int n_in,
                              void* d_out, int out_size) {
    const float* x = (const float*)d_in[0];   // [4,3,256,256]
    const float* y = (const float*)d_in[1];   // [4,2,256,256]
    float* out = (float*)d_out;

    dim3 grid(GX, GY, B);
    potts_fused<<<grid, NTHR>>>(x, y, out);
}